// round 11
// baseline (speedup 1.0000x reference)
#include <cuda_runtime.h>
#include <cstdint>

#define THRESH      0.7f
#define MIN_KEPT    100000
#define IGNORE_LBL  (-100.0f)
#define LOG_CLAMP   (-100.0f)
#define LN2F        0.6931471805599453f
#define LOG2_CLAMP  (-144.26950408889634f)   /* -100 / ln2 */

// ---------------- device state (reset-after-use; zero-init at load) ----------
__device__ double        g_sum_lt    = 0.0;  // loss sum: valid & p < 0.7
__device__ int           g_cnt_valid = 0;
__device__ int           g_cnt_lt    = 0;    // valid & p < 0.7
__device__ int           g_cnt_eq    = 0;    // valid & p == 0.7
__device__ unsigned int  g_done      = 0;    // block retirement counter
__device__ unsigned int  g_hist[65536];      // refine path only (zeroed there)

// ------------------------------- helpers ------------------------------------
// Hot-path BCE in log2 domain (caller scales the accumulated sum by ln2 once).
// Valid ONLY for p < THRESH: then 1-p > 0.3, so the torch -100 clamp on
// log1p(-p) can never bind and is omitted. The clamp on log(p) is kept
// (applied in log2 units).
__device__ __forceinline__ float bce_log2_lt(float p, float t, float w) {
    float lp = fmaxf(__log2f(p), LOG2_CLAMP);
    float l1 = __log2f(1.0f - p);
    // returns  -w * (t*(lp-l1) + l1)   [log2 units]
    return -w * fmaf(t, lp - l1, l1);
}

// Cold-path exact BCE (natural log, both clamps) for the refine band.
__device__ __forceinline__ float bce_full(float p, float t, float w) {
    float lp = fmaxf(__logf(p),        LOG_CLAMP);
    float l1 = fmaxf(__logf(1.0f - p), LOG_CLAMP);
    return -w * fmaf(t, lp - l1, l1);
}

// ---------------- single fused kernel: stream + decide + (cold) refine -------
__global__ void __launch_bounds__(256, 8) k_fused(
    const float* __restrict__ P, const float* __restrict__ T,
    const float* __restrict__ W, float* __restrict__ out, int n)
{
    const int tid    = blockIdx.x * blockDim.x + threadIdx.x;
    const int stride = gridDim.x * blockDim.x;
    const int nvec   = n >> 2;

    const float4* __restrict__ P4 = (const float4*)P;
    const float4* __restrict__ T4 = (const float4*)T;
    const float4* __restrict__ W4 = (const float4*)W;

    float sum = 0.0f;                    // in log2 units until scaled below
    int cv = 0, clt = 0, ceq = 0;

#define LANE(px, tx, wx)                                                    \
    {                                                                       \
        bool valid = ((tx) != IGNORE_LBL);                                  \
        bool lt    = valid & ((px) < THRESH);                               \
        cv  += valid;                                                       \
        clt += lt;                                                          \
        ceq += valid & ((px) == THRESH);                                    \
        if (lt) sum += bce_log2_lt((px), (tx), (wx));                       \
    }

    int i = tid;
    // unroll-by-2: 6 independent streaming float4 loads in flight,
    // register budget sized for 8 blocks/SM residency.
    for (; i + stride < nvec; i += 2 * stride) {
        float4 p0 = __ldcs(P4 + i); float4 p1 = __ldcs(P4 + i + stride);
        float4 t0 = __ldcs(T4 + i); float4 t1 = __ldcs(T4 + i + stride);
        float4 w0 = __ldcs(W4 + i); float4 w1 = __ldcs(W4 + i + stride);
        LANE(p0.x, t0.x, w0.x) LANE(p0.y, t0.y, w0.y)
        LANE(p0.z, t0.z, w0.z) LANE(p0.w, t0.w, w0.w)
        LANE(p1.x, t1.x, w1.x) LANE(p1.y, t1.y, w1.y)
        LANE(p1.z, t1.z, w1.z) LANE(p1.w, t1.w, w1.w)
    }
    for (; i < nvec; i += stride) {
        float4 p = __ldcs(P4 + i); float4 t = __ldcs(T4 + i); float4 w = __ldcs(W4 + i);
        LANE(p.x, t.x, w.x) LANE(p.y, t.y, w.y)
        LANE(p.z, t.z, w.z) LANE(p.w, t.w, w.w)
    }
    // scalar tail (n not multiple of 4)
    for (int j = (nvec << 2) + tid; j < n; j += stride) {
        float pv = P[j], tv = T[j], wv = W[j];
        LANE(pv, tv, wv)
    }
#undef LANE

    sum *= LN2F;                          // back to natural-log units, once

    // block reduction: warp shuffles -> shared -> per-block atomics
    const unsigned full = 0xFFFFFFFFu;
    for (int o = 16; o; o >>= 1) {
        sum += __shfl_down_sync(full, sum, o);
        cv  += __shfl_down_sync(full, cv,  o);
        clt += __shfl_down_sync(full, clt, o);
        ceq += __shfl_down_sync(full, ceq, o);
    }
    __shared__ float ss[8];
    __shared__ int   sv[8], sl[8], se[8];
    int lane = threadIdx.x & 31, wid = threadIdx.x >> 5;
    if (lane == 0) { ss[wid] = sum; sv[wid] = cv; sl[wid] = clt; se[wid] = ceq; }
    __syncthreads();
    if (wid == 0) {
        int nw = blockDim.x >> 5;
        sum = (lane < nw) ? ss[lane] : 0.0f;
        cv  = (lane < nw) ? sv[lane] : 0;
        clt = (lane < nw) ? sl[lane] : 0;
        ceq = (lane < nw) ? se[lane] : 0;
        for (int o = 4; o; o >>= 1) {
            sum += __shfl_down_sync(full, sum, o);
            cv  += __shfl_down_sync(full, cv,  o);
            clt += __shfl_down_sync(full, clt, o);
            ceq += __shfl_down_sync(full, ceq, o);
        }
        if (lane == 0) {
            atomicAdd(&g_sum_lt, (double)sum);
            atomicAdd(&g_cnt_valid, cv);
            atomicAdd(&g_cnt_lt, clt);
            if (ceq) atomicAdd(&g_cnt_eq, ceq);
        }
    }

    // ---- last-block-done: decision epilogue (whole block participates) ----
    __shared__ bool s_last;
    if (threadIdx.x == 0) {
        __threadfence();
        unsigned t = atomicAdd(&g_done, 1u);
        s_last = (t == gridDim.x - 1);
    }
    __syncthreads();
    if (!s_last) return;                 // block-uniform: barriers below are safe

    __shared__ int       s_refine;
    __shared__ unsigned  s_rank;         // rank within the p >= 0.7 region
    __shared__ double    s_base_sum;
    __shared__ int       s_base_cnt;
    if (threadIdx.x == 0) {
        g_done = 0u;
        long long nv = (long long)g_cnt_valid;
        long long k  = nv - 1;
        if (k > (long long)MIN_KEPT) k = MIN_KEPT;
        long long lt = (long long)g_cnt_lt;
        // sort_p[k] <= 0.7  <=>  count(valid & p <= 0.7) >= k+1 => thr == 0.7
        if (lt + (long long)g_cnt_eq >= k + 1) {
            out[0] = (float)(g_sum_lt / (double)lt);
            s_refine = 0;
        } else {
            s_refine    = 1;
            s_rank      = (unsigned)(k - lt);
            s_base_sum  = g_sum_lt;
            s_base_cnt  = (int)lt;
        }
        g_sum_lt = 0.0; g_cnt_lt = 0; g_cnt_valid = 0; g_cnt_eq = 0;
    }
    __syncthreads();
    if (!s_refine) return;

    // ---- cold refinement path: exact k-th smallest among p >= 0.7 ----------
    // Never taken for the benchmark distribution; correct-but-slow fallback.
    const int t0 = threadIdx.x, nt = blockDim.x;

    // phase 1: high-16-bit histogram
    for (int j = t0; j < 65536; j += nt) g_hist[j] = 0u;
    __syncthreads();
    for (int j = t0; j < n; j += nt) {
        float tv = T[j], pv = P[j];
        if (tv != IGNORE_LBL && pv >= THRESH)
            atomicAdd(&g_hist[__float_as_uint(pv) >> 16], 1u);
    }
    __syncthreads();
    __shared__ unsigned s_bin, s_rlo;
    if (t0 == 0) {
        unsigned cum = 0, r = s_rank;
        for (int b = 0; b < 65536; b++) {
            unsigned c = g_hist[b];
            if (cum + c > r) { s_bin = (unsigned)b; s_rlo = r - cum; break; }
            cum += c;
        }
    }
    __syncthreads();

    // phase 2: low-16-bit histogram within the winning bin
    unsigned bh = s_bin;
    for (int j = t0; j < 65536; j += nt) g_hist[j] = 0u;
    __syncthreads();
    for (int j = t0; j < n; j += nt) {
        float tv = T[j], pv = P[j];
        if (tv != IGNORE_LBL && pv >= THRESH) {
            unsigned b = __float_as_uint(pv);
            if ((b >> 16) == bh) atomicAdd(&g_hist[b & 0xFFFFu], 1u);
        }
    }
    __syncthreads();
    __shared__ float s_T;
    if (t0 == 0) {
        unsigned cum = 0, r = s_rlo;
        for (int l = 0; l < 65536; l++) {
            unsigned c = g_hist[l];
            if (cum + c > r) { s_T = __uint_as_float((bh << 16) | (unsigned)l); break; }
            cum += c;
        }
    }
    __syncthreads();

    // phase 3: loss over the [0.7, T) band
    float Tv = s_T;
    float rs = 0.0f; int rc = 0;
    for (int j = t0; j < n; j += nt) {
        float tv = T[j], pv = P[j];
        if (tv != IGNORE_LBL && pv >= THRESH && pv < Tv) {
            rs += bce_full(pv, tv, W[j]);
            rc++;
        }
    }
    for (int o = 16; o; o >>= 1) {
        rs += __shfl_down_sync(full, rs, o);
        rc += __shfl_down_sync(full, rc, o);
    }
    __shared__ float rss[8];
    __shared__ int   rsc[8];
    if (lane == 0) { rss[wid] = rs; rsc[wid] = rc; }
    __syncthreads();
    if (t0 == 0) {
        double tot = s_base_sum; int cnt = s_base_cnt;
        int nw = nt >> 5;
        for (int q = 0; q < nw; q++) { tot += (double)rss[q]; cnt += rsc[q]; }
        out[0] = (float)(tot / (double)cnt);
    }
}

// ------------------------------- launcher -----------------------------------
extern "C" void kernel_launch(void* const* d_in, const int* in_sizes, int n_in,
                              void* d_out, int out_size)
{
    const float* P = (const float*)d_in[0];   // predict
    const float* T = (const float*)d_in[1];   // target
    const float* W = (const float*)d_in[2];   // weight
    float* out = (float*)d_out;
    int n = in_sizes[0];

    int nvec = n >> 2;
    int blocks = (nvec + 255) / 256;
    if (blocks > 8192) blocks = 8192;
    if (blocks < 1) blocks = 1;

    k_fused<<<blocks, 256>>>(P, T, W, out, n);
}

// round 13
// speedup vs baseline: 1.0590x; 1.0590x over previous
#include <cuda_runtime.h>
#include <cstdint>

#define THRESH      0.7f
#define MIN_KEPT    100000
#define IGNORE_LBL  (-100.0f)
#define LOG_CLAMP   (-100.0f)
#define LN2F        0.6931471805599453f
#define LOG2_CLAMP  (-144.26950408889634f)   /* -100 / ln2 */

// ---------------- device state (reset-after-use; zero-init at load) ----------
__device__ double        g_sum_lt    = 0.0;  // loss sum: valid & p < 0.7
__device__ int           g_cnt_valid = 0;
__device__ int           g_cnt_lt    = 0;    // valid & p < 0.7
__device__ int           g_cnt_eq    = 0;    // valid & p == 0.7
__device__ unsigned int  g_done      = 0;    // block retirement counter
__device__ unsigned int  g_hist[65536];      // refine path only (zeroed there)

// ------------------------------- helpers ------------------------------------
// Hot-path BCE in log2 domain (caller scales the accumulated sum by ln2 once).
// Valid ONLY for p < THRESH: then 1-p > 0.3, so the torch -100 clamp on
// log1p(-p) can never bind and is omitted. The clamp on log(p) is kept
// (applied in log2 units).
__device__ __forceinline__ float bce_log2_lt(float p, float t, float w) {
    float lp = fmaxf(__log2f(p), LOG2_CLAMP);
    float l1 = __log2f(1.0f - p);
    return -w * fmaf(t, lp - l1, l1);      // log2 units
}

// Cold-path exact BCE (natural log, both clamps) for the refine band.
__device__ __forceinline__ float bce_full(float p, float t, float w) {
    float lp = fmaxf(__logf(p),        LOG_CLAMP);
    float l1 = fmaxf(__logf(1.0f - p), LOG_CLAMP);
    return -w * fmaf(t, lp - l1, l1);
}

// ---------------- single fused kernel: stream + decide + (cold) refine -------
// 6 CTAs/SM (reg budget 42): proven sweet spot — keeps 6 float4 loads in
// flight per thread while holding ~72% occupancy. Grid is ONE wave (148*6
// blocks), so there are no wave transitions; each thread iterates ~37 times.
__global__ void __launch_bounds__(256, 6) k_fused(
    const float* __restrict__ P, const float* __restrict__ T,
    const float* __restrict__ W, float* __restrict__ out, int n)
{
    const int tid    = blockIdx.x * blockDim.x + threadIdx.x;
    const int stride = gridDim.x * blockDim.x;
    const int nvec   = n >> 2;

    const float4* __restrict__ P4 = (const float4*)P;
    const float4* __restrict__ T4 = (const float4*)T;
    const float4* __restrict__ W4 = (const float4*)W;

    float sum = 0.0f;                    // log2 units until scaled below
    int cv = 0, clt = 0, ceq = 0;

#define LANE(px, tx, wx)                                                    \
    {                                                                       \
        bool valid = ((tx) != IGNORE_LBL);                                  \
        bool lt    = valid & ((px) < THRESH);                               \
        cv  += valid;                                                       \
        clt += lt;                                                          \
        ceq += valid & ((px) == THRESH);                                    \
        if (lt) sum += bce_log2_lt((px), (tx), (wx));                       \
    }

    int i = tid;
    // unroll-by-2: 6 independent streaming float4 loads in flight
    for (; i + stride < nvec; i += 2 * stride) {
        float4 p0 = __ldcs(P4 + i); float4 p1 = __ldcs(P4 + i + stride);
        float4 t0 = __ldcs(T4 + i); float4 t1 = __ldcs(T4 + i + stride);
        float4 w0 = __ldcs(W4 + i); float4 w1 = __ldcs(W4 + i + stride);
        LANE(p0.x, t0.x, w0.x) LANE(p0.y, t0.y, w0.y)
        LANE(p0.z, t0.z, w0.z) LANE(p0.w, t0.w, w0.w)
        LANE(p1.x, t1.x, w1.x) LANE(p1.y, t1.y, w1.y)
        LANE(p1.z, t1.z, w1.z) LANE(p1.w, t1.w, w1.w)
    }
    for (; i < nvec; i += stride) {
        float4 p = __ldcs(P4 + i); float4 t = __ldcs(T4 + i); float4 w = __ldcs(W4 + i);
        LANE(p.x, t.x, w.x) LANE(p.y, t.y, w.y)
        LANE(p.z, t.z, w.z) LANE(p.w, t.w, w.w)
    }
    // scalar tail (n not multiple of 4)
    for (int j = (nvec << 2) + tid; j < n; j += stride) {
        float pv = P[j], tv = T[j], wv = W[j];
        LANE(pv, tv, wv)
    }
#undef LANE

    sum *= LN2F;                          // back to natural-log units, once

    // block reduction: warp shuffles -> shared -> per-block atomics
    const unsigned full = 0xFFFFFFFFu;
    for (int o = 16; o; o >>= 1) {
        sum += __shfl_down_sync(full, sum, o);
        cv  += __shfl_down_sync(full, cv,  o);
        clt += __shfl_down_sync(full, clt, o);
        ceq += __shfl_down_sync(full, ceq, o);
    }
    __shared__ float ss[8];
    __shared__ int   sv[8], sl[8], se[8];
    int lane = threadIdx.x & 31, wid = threadIdx.x >> 5;
    if (lane == 0) { ss[wid] = sum; sv[wid] = cv; sl[wid] = clt; se[wid] = ceq; }
    __syncthreads();
    if (wid == 0) {
        int nw = blockDim.x >> 5;
        sum = (lane < nw) ? ss[lane] : 0.0f;
        cv  = (lane < nw) ? sv[lane] : 0;
        clt = (lane < nw) ? sl[lane] : 0;
        ceq = (lane < nw) ? se[lane] : 0;
        for (int o = 4; o; o >>= 1) {
            sum += __shfl_down_sync(full, sum, o);
            cv  += __shfl_down_sync(full, cv,  o);
            clt += __shfl_down_sync(full, clt, o);
            ceq += __shfl_down_sync(full, ceq, o);
        }
        if (lane == 0) {
            atomicAdd(&g_sum_lt, (double)sum);
            atomicAdd(&g_cnt_valid, cv);
            atomicAdd(&g_cnt_lt, clt);
            if (ceq) atomicAdd(&g_cnt_eq, ceq);
        }
    }

    // ---- last-block-done: decision epilogue (whole block participates) ----
    __shared__ bool s_last;
    if (threadIdx.x == 0) {
        __threadfence();
        unsigned t = atomicAdd(&g_done, 1u);
        s_last = (t == gridDim.x - 1);
    }
    __syncthreads();
    if (!s_last) return;                 // block-uniform: barriers below are safe

    __shared__ int       s_refine;
    __shared__ unsigned  s_rank;         // rank within the p >= 0.7 region
    __shared__ double    s_base_sum;
    __shared__ int       s_base_cnt;
    if (threadIdx.x == 0) {
        g_done = 0u;
        long long nv = (long long)g_cnt_valid;
        long long k  = nv - 1;
        if (k > (long long)MIN_KEPT) k = MIN_KEPT;
        long long lt = (long long)g_cnt_lt;
        // sort_p[k] <= 0.7  <=>  count(valid & p <= 0.7) >= k+1 => thr == 0.7
        if (lt + (long long)g_cnt_eq >= k + 1) {
            out[0] = (float)(g_sum_lt / (double)lt);
            s_refine = 0;
        } else {
            s_refine    = 1;
            s_rank      = (unsigned)(k - lt);
            s_base_sum  = g_sum_lt;
            s_base_cnt  = (int)lt;
        }
        g_sum_lt = 0.0; g_cnt_lt = 0; g_cnt_valid = 0; g_cnt_eq = 0;
    }
    __syncthreads();
    if (!s_refine) return;

    // ---- cold refinement path: exact k-th smallest among p >= 0.7 ----------
    // Never taken for the benchmark distribution; correct-but-slow fallback.
    const int t0 = threadIdx.x, nt = blockDim.x;

    // phase 1: high-16-bit histogram
    for (int j = t0; j < 65536; j += nt) g_hist[j] = 0u;
    __syncthreads();
    for (int j = t0; j < n; j += nt) {
        float tv = T[j], pv = P[j];
        if (tv != IGNORE_LBL && pv >= THRESH)
            atomicAdd(&g_hist[__float_as_uint(pv) >> 16], 1u);
    }
    __syncthreads();
    __shared__ unsigned s_bin, s_rlo;
    if (t0 == 0) {
        unsigned cum = 0, r = s_rank;
        for (int b = 0; b < 65536; b++) {
            unsigned c = g_hist[b];
            if (cum + c > r) { s_bin = (unsigned)b; s_rlo = r - cum; break; }
            cum += c;
        }
    }
    __syncthreads();

    // phase 2: low-16-bit histogram within the winning bin
    unsigned bh = s_bin;
    for (int j = t0; j < 65536; j += nt) g_hist[j] = 0u;
    __syncthreads();
    for (int j = t0; j < n; j += nt) {
        float tv = T[j], pv = P[j];
        if (tv != IGNORE_LBL && pv >= THRESH) {
            unsigned b = __float_as_uint(pv);
            if ((b >> 16) == bh) atomicAdd(&g_hist[b & 0xFFFFu], 1u);
        }
    }
    __syncthreads();
    __shared__ float s_T;
    if (t0 == 0) {
        unsigned cum = 0, r = s_rlo;
        for (int l = 0; l < 65536; l++) {
            unsigned c = g_hist[l];
            if (cum + c > r) { s_T = __uint_as_float((bh << 16) | (unsigned)l); break; }
            cum += c;
        }
    }
    __syncthreads();

    // phase 3: loss over the [0.7, T) band
    float Tv = s_T;
    float rs = 0.0f; int rc = 0;
    for (int j = t0; j < n; j += nt) {
        float tv = T[j], pv = P[j];
        if (tv != IGNORE_LBL && pv >= THRESH && pv < Tv) {
            rs += bce_full(pv, tv, W[j]);
            rc++;
        }
    }
    for (int o = 16; o; o >>= 1) {
        rs += __shfl_down_sync(full, rs, o);
        rc += __shfl_down_sync(full, rc, o);
    }
    __shared__ float rss[8];
    __shared__ int   rsc[8];
    if (lane == 0) { rss[wid] = rs; rsc[wid] = rc; }
    __syncthreads();
    if (t0 == 0) {
        double tot = s_base_sum; int cnt = s_base_cnt;
        int nw = nt >> 5;
        for (int q = 0; q < nw; q++) { tot += (double)rss[q]; cnt += rsc[q]; }
        out[0] = (float)(tot / (double)cnt);
    }
}

// ------------------------------- launcher -----------------------------------
extern "C" void kernel_launch(void* const* d_in, const int* in_sizes, int n_in,
                              void* d_out, int out_size)
{
    const float* P = (const float*)d_in[0];   // predict
    const float* T = (const float*)d_in[1];   // target
    const float* W = (const float*)d_in[2];   // weight
    float* out = (float*)d_out;
    int n = in_sizes[0];

    // Exactly one wave: 148 SMs x 6 resident CTAs/SM.
    int blocks = 148 * 6;                     // 888
    int nvec = n >> 2;
    int need = (nvec + 255) / 256;
    if (need < 1) need = 1;
    if (blocks > need) blocks = need;

    k_fused<<<blocks, 256>>>(P, T, W, out, n);
}